// round 17
// baseline (speedup 1.0000x reference)
#include <cuda_runtime.h>

// SlidingWindow: k,v (1, 2048, 16, 64) fp32, W=64
// out = concat(k_win, v_win), each (1, 2048, 16, 64, 64) fp32 layout [t][h][w][d]
// out_k[t,h,w,d] = (w < min(t+1,W)) ? k[max(0,t+1-W)+w, h, d] : 0
//
// Experiment: persistent grid-stride launch. Same per-tile memory shape as
// the converged 145.9us config (1024 float4/tile, block-strided coalescing,
// __stcs, fast/slow split), but grid = 1184 CTAs (148 SMs x 8) looping over
// all 32768 tiles -> zero wave transitions, zero CTA churn.

#define H_DIM 16
#define W_DIM 64

// per-tensor float4 count: 2048*16*64*64/4 = 33,554,432
#define N4 33554432LL

#define TPB 128
#define ILP 8
#define TILE_F4 (TPB * ILP)          // 1024 float4 per tile
#define NUM_TILES 32768              // N4 / TILE_F4
// one t-slice = 16384 float4s = 16 tiles; tiles >= 63*16 = 1008 -> full window.
#define FIRST_ALL_VALID_TILE 1008

#define GRID_BLOCKS 1184             // 148 SMs * 8 resident CTAs

__global__ __launch_bounds__(TPB) void sliding_window_kernel(
    const float4* __restrict__ k4,
    const float4* __restrict__ v4,
    float4* __restrict__ out4)   // [0, N4) = k_win, [N4, 2N4) = v_win
{
    for (int tile = blockIdx.x; tile < NUM_TILES; tile += GRID_BLOCKS) {
        const long long blk = (long long)tile * TILE_F4 + threadIdx.x;

        long long src[ILP];
        float4 kk[ILP], vv[ILP];

        if (tile >= FIRST_ALL_VALID_TILE) {
            // fast path: t >= 63, window always full, no predication.
#pragma unroll
            for (int j = 0; j < ILP; j++) {
                const long long i = blk + (long long)j * TPB;
                const int d4 = (int)(i & 15);
                const int w  = (int)((i >> 4) & 63);
                const int h  = (int)((i >> 10) & 15);
                const int t  = (int)(i >> 14);
                const int src_t = t + 1 - W_DIM + w;
                src[j] = (((long long)src_t * H_DIM + h) << 4) + d4;
            }
#pragma unroll
            for (int j = 0; j < ILP; j++) kk[j] = __ldg(&k4[src[j]]);
#pragma unroll
            for (int j = 0; j < ILP; j++) vv[j] = __ldg(&v4[src[j]]);
        } else {
            // slow path: t < 63, window may be partial (zero-fill; start = 0).
            const float4 z = make_float4(0.f, 0.f, 0.f, 0.f);
            bool valid[ILP];
#pragma unroll
            for (int j = 0; j < ILP; j++) {
                const long long i = blk + (long long)j * TPB;
                const int d4 = (int)(i & 15);
                const int w  = (int)((i >> 4) & 63);
                const int h  = (int)((i >> 10) & 15);
                const int t  = (int)(i >> 14);
                valid[j] = (w <= t);
                src[j] = (((long long)w * H_DIM + h) << 4) + d4;
            }
#pragma unroll
            for (int j = 0; j < ILP; j++) kk[j] = valid[j] ? __ldg(&k4[src[j]]) : z;
#pragma unroll
            for (int j = 0; j < ILP; j++) vv[j] = valid[j] ? __ldg(&v4[src[j]]) : z;
        }

#pragma unroll
        for (int j = 0; j < ILP; j++)
            __stcs(&out4[blk + (long long)j * TPB], kk[j]);   // evict-first stream
#pragma unroll
        for (int j = 0; j < ILP; j++)
            __stcs(&out4[blk + (long long)j * TPB + N4], vv[j]);
    }
}

extern "C" void kernel_launch(void* const* d_in, const int* in_sizes, int n_in,
                              void* d_out, int out_size) {
    const float4* k4 = (const float4*)d_in[0];
    const float4* v4 = (const float4*)d_in[1];
    float4* out4 = (float4*)d_out;

    sliding_window_kernel<<<GRID_BLOCKS, TPB>>>(k4, v4, out4);
}